// round 5
// baseline (speedup 1.0000x reference)
#include <cuda_runtime.h>
#include <math.h>

#define BATCH 128
#define NN 256
#define EMB 256
#define LD 512
#define TST 256
#define G4 2048

__device__ float g_G[(size_t)BATCH*2*NN*EMB];
__device__ float g_S[(size_t)BATCH*NN*NN];
__device__ float g_XP[(size_t)BATCH*TST*G4];
__device__ float g_HS[(size_t)BATCH*TST*LD];
__device__ float g_H[BATCH*LD];
__device__ float g_C[BATCH*LD];
__device__ float g_P[2*BATCH*G4];
__device__ float g_K[(size_t)BATCH*NN*NN];
__device__ float g_u[BATCH*NN];
__device__ float g_v[BATCH*NN];

__device__ __forceinline__ unsigned long long pk2(float lo, float hi) {
    unsigned long long r;
    asm("mov.b64 %0, {%1, %2};" : "=l"(r) : "f"(lo), "f"(hi));
    return r;
}
__device__ __forceinline__ void upk2(unsigned long long v, float &lo, float &hi) {
    asm("mov.b64 {%0, %1}, %2;" : "=f"(lo), "=f"(hi) : "l"(v));
}
__device__ __forceinline__ void fma2(unsigned long long &d, unsigned long long a,
                                     unsigned long long b) {
    asm("fma.rn.f32x2 %0, %1, %2, %0;" : "+l"(d) : "l"(a), "l"(b));
}

// ---------------- embedding + leaky relu ------------------------------------
__global__ void __launch_bounds__(256) embed_kernel(
    const float* __restrict__ x, const float* __restrict__ W_emb,
    const float* __restrict__ b_emb)
{
    __shared__ float sW[32 * 256];
    __shared__ float sx[16 * 32];
    int tid = threadIdx.x;
    int b = blockIdx.y;
    int p0 = blockIdx.x * 16;
    for (int idx = tid; idx < 256 * 32; idx += 256) {
        int e = idx >> 5, f = idx & 31;
        sW[f * 256 + e] = W_emb[idx];
    }
    for (int idx = tid; idx < 512; idx += 256)
        sx[idx] = x[((size_t)b * 512 + p0) * 32 + idx];
    __syncthreads();
    int e = tid;
    float bias = b_emb[e];
    float acc[16];
#pragma unroll
    for (int r = 0; r < 16; ++r) acc[r] = bias;
#pragma unroll
    for (int f = 0; f < 32; ++f) {
        float w = sW[f * 256 + e];
#pragma unroll
        for (int r = 0; r < 16; ++r) acc[r] += sx[r * 32 + f] * w;
    }
#pragma unroll
    for (int r = 0; r < 16; ++r) {
        float v = acc[r];
        v = (v > 0.f) ? v : 0.01f * v;
        g_G[((size_t)b * 512 + p0 + r) * 256 + e] = v;
    }
}

// ---------------- generic NT GEMM: C[m,n] = sum_k A[m,k]*B[n,k] -------------
// 64x64 tile, 256 threads, 4x4 microtile, packed f32x2 FMA.
// blockIdx.z: batch (via *bat strides) OR split-K (via kstep k-offset).
// MODE 0: plain  MODE 1: +b1[n]+b2[n]  MODE 2: exp(acc + b1[n])
template <int MODE>
__global__ void __launch_bounds__(256) gemm_nt(
    const float* __restrict__ A, int ldA, size_t Abat,
    const float* __restrict__ B, int ldB, size_t Bbat,
    const float* __restrict__ b1, const float* __restrict__ b2,
    float* __restrict__ C, int ldC, size_t Cbat, int Kloop, int kstep)
{
    __shared__ __align__(16) float As[16 * 64];
    __shared__ __align__(16) float Bs[16 * 64];
    int tid = threadIdx.x;
    int tx = tid & 15, ty = tid >> 4;
    size_t zo = blockIdx.z;
    A += zo * Abat + zo * (size_t)kstep + (size_t)blockIdx.y * 64 * ldA;
    B += zo * Bbat + zo * (size_t)kstep + (size_t)blockIdx.x * 64 * ldB;
    C += zo * Cbat + (size_t)blockIdx.y * 64 * ldC + (size_t)blockIdx.x * 64;
    int ar = tid >> 2, aq = (tid & 3) * 4;

    unsigned long long acc[4][2];
#pragma unroll
    for (int i = 0; i < 4; ++i) { acc[i][0] = 0ULL; acc[i][1] = 0ULL; }

    for (int kt = 0; kt < Kloop; kt += 16) {
        float4 av = *(const float4*)(A + (size_t)ar * ldA + kt + aq);
        float4 bv = *(const float4*)(B + (size_t)ar * ldB + kt + aq);
        __syncthreads();
        As[(aq + 0) * 64 + ar] = av.x;
        As[(aq + 1) * 64 + ar] = av.y;
        As[(aq + 2) * 64 + ar] = av.z;
        As[(aq + 3) * 64 + ar] = av.w;
        Bs[(aq + 0) * 64 + ar] = bv.x;
        Bs[(aq + 1) * 64 + ar] = bv.y;
        Bs[(aq + 2) * 64 + ar] = bv.z;
        Bs[(aq + 3) * 64 + ar] = bv.w;
        __syncthreads();
#pragma unroll
        for (int kk = 0; kk < 16; ++kk) {
            float4 a4 = *(const float4*)&As[kk * 64 + ty * 4];
            float4 b4 = *(const float4*)&Bs[kk * 64 + tx * 4];
            unsigned long long bp0 = pk2(b4.x, b4.y);
            unsigned long long bp1 = pk2(b4.z, b4.w);
            unsigned long long ap;
            ap = pk2(a4.x, a4.x); fma2(acc[0][0], ap, bp0); fma2(acc[0][1], ap, bp1);
            ap = pk2(a4.y, a4.y); fma2(acc[1][0], ap, bp0); fma2(acc[1][1], ap, bp1);
            ap = pk2(a4.z, a4.z); fma2(acc[2][0], ap, bp0); fma2(acc[2][1], ap, bp1);
            ap = pk2(a4.w, a4.w); fma2(acc[3][0], ap, bp0); fma2(acc[3][1], ap, bp1);
        }
    }
    int gn = blockIdx.x * 64 + tx * 4;
#pragma unroll
    for (int i = 0; i < 4; ++i) {
        float r0, r1, r2, r3;
        upk2(acc[i][0], r0, r1);
        upk2(acc[i][1], r2, r3);
        if (MODE == 1) {
            r0 += b1[gn + 0] + b2[gn + 0];
            r1 += b1[gn + 1] + b2[gn + 1];
            r2 += b1[gn + 2] + b2[gn + 2];
            r3 += b1[gn + 3] + b2[gn + 3];
        }
        if (MODE == 2) {
            r0 = expf(r0 + b1[gn + 0]);
            r1 = expf(r1 + b1[gn + 1]);
            r2 = expf(r2 + b1[gn + 2]);
            r3 = expf(r3 + b1[gn + 3]);
        }
        float4 o; o.x = r0; o.y = r1; o.z = r2; o.w = r3;
        *(float4*)(C + (size_t)(ty * 4 + i) * ldC + tx * 4) = o;
    }
}

// ---------------- init h=c=0, v=1 -------------------------------------------
__global__ void init_k() {
    int i = blockIdx.x * 256 + threadIdx.x;
    if (i < BATCH * LD) { g_H[i] = 0.f; g_C[i] = 0.f; }
    if (i < BATCH * NN) g_v[i] = 1.f;
}

// ---------------- LSTM gate update ------------------------------------------
__global__ void __launch_bounds__(256) lstm_update(int t) {
    int idx = blockIdx.x * 256 + threadIdx.x;   // 65536 = 128*512
    int b = idx >> 9, j = idx & 511;
    size_t base = (size_t)b * G4;
    size_t xb = ((size_t)b * TST + t) * G4;
    const float* P0 = g_P;
    const float* P1 = g_P + (size_t)BATCH * G4;
    float gi = P0[base + j]        + P1[base + j]        + g_XP[xb + j];
    float gf = P0[base + 512 + j]  + P1[base + 512 + j]  + g_XP[xb + 512 + j];
    float gg = P0[base + 1024 + j] + P1[base + 1024 + j] + g_XP[xb + 1024 + j];
    float go = P0[base + 1536 + j] + P1[base + 1536 + j] + g_XP[xb + 1536 + j];
    float i_ = 1.f / (1.f + __expf(-gi));
    float f_ = 1.f / (1.f + __expf(-gf));
    float o_ = 1.f / (1.f + __expf(-go));
    float g_ = tanhf(gg);
    float c = f_ * g_C[b * LD + j] + i_ * g_;
    float h = o_ * tanhf(c);
    g_C[b * LD + j] = c;
    g_H[b * LD + j] = h;
    g_HS[((size_t)b * TST + t) * LD + j] = h;
}

// ---------------- Sinkhorn --------------------------------------------------
__global__ void sink_row() {   // u = 1 / (K v)
    int b = blockIdx.y;
    int m = blockIdx.x * 8 + (threadIdx.x >> 5);
    int lane = threadIdx.x & 31;
    const float* Kr = g_K + ((size_t)b * NN + m) * NN;
    const float* vv = g_v + b * NN;
    float acc = 0.f;
#pragma unroll
    for (int i = 0; i < 8; ++i) acc += Kr[lane + 32 * i] * vv[lane + 32 * i];
#pragma unroll
    for (int o = 16; o; o >>= 1) acc += __shfl_xor_sync(0xFFFFFFFFu, acc, o);
    if (!lane) g_u[b * NN + m] = 1.f / acc;
}

__global__ void sink_col() {   // v = 1 / (K^T u)
    int b = blockIdx.y;
    int n = blockIdx.x * 64 + (threadIdx.x & 63);
    int part = threadIdx.x >> 6;
    const float* Kb = g_K + (size_t)b * NN * NN;
    const float* uu = g_u + b * NN;
    float acc = 0.f;
    for (int m = part; m < NN; m += 4) acc += Kb[(size_t)m * NN + n] * uu[m];
    __shared__ float s[256];
    s[threadIdx.x] = acc;
    __syncthreads();
    if (threadIdx.x < 64) {
        float r = s[threadIdx.x] + s[threadIdx.x + 64] + s[threadIdx.x + 128] +
                  s[threadIdx.x + 192];
        g_v[b * NN + n] = 1.f / r;
    }
}

__global__ void sink_out(float* __restrict__ out) {
    int b = blockIdx.y, m = blockIdx.x, n = threadIdx.x;
    size_t o = ((size_t)b * NN + m) * NN + n;
    out[o] = g_u[b * NN + m] * g_K[o] * g_v[b * NN + n];
}

// ---------------------------------------------------------------------------
extern "C" void kernel_launch(void* const* d_in, const int* in_sizes, int n_in,
                              void* d_out, int out_size)
{
    const float* x     = (const float*)d_in[0];
    const float* W_emb = (const float*)d_in[1];
    const float* b_emb = (const float*)d_in[2];
    const float* W_ih  = (const float*)d_in[3];
    const float* W_hh  = (const float*)d_in[4];
    const float* b_ih  = (const float*)d_in[5];
    const float* b_hh  = (const float*)d_in[6];
    const float* W_fc  = (const float*)d_in[7];
    const float* b_fc  = (const float*)d_in[8];
    float* out = (float*)d_out;

    float *gG, *gS, *gXP, *gHS, *gH, *gP, *gK;
    cudaGetSymbolAddress((void**)&gG,  g_G);
    cudaGetSymbolAddress((void**)&gS,  g_S);
    cudaGetSymbolAddress((void**)&gXP, g_XP);
    cudaGetSymbolAddress((void**)&gHS, g_HS);
    cudaGetSymbolAddress((void**)&gH,  g_H);
    cudaGetSymbolAddress((void**)&gP,  g_P);
    cudaGetSymbolAddress((void**)&gK,  g_K);

    init_k<<<256, 256>>>();
    embed_kernel<<<dim3(32, 128), 256>>>(x, W_emb, b_emb);

    // S[b] = g2[b] @ g1[b]^T   (M=256, N=256, K=256, batched over b)
    gemm_nt<0><<<dim3(4, 4, 128), 256>>>(
        gG + (size_t)NN * EMB, EMB, (size_t)2 * NN * EMB,
        gG, EMB, (size_t)2 * NN * EMB,
        nullptr, nullptr, gS, NN, (size_t)NN * NN, EMB, 0);

    // XP[b*256+t, :] = S[b,t,:] @ W_ih^T + b_ih + b_hh  (M=32768, N=2048, K=256)
    gemm_nt<1><<<dim3(32, 512, 1), 256>>>(
        gS, NN, 0, W_ih, NN, 0, b_ih, b_hh, gXP, G4, 0, NN, 0);

    // LSTM: 256 sequential steps; split-K=2 recurrent GEMM + fused update
    for (int t = 0; t < TST; ++t) {
        gemm_nt<0><<<dim3(32, 2, 2), 256>>>(
            gH, LD, 0, W_hh, LD, 0, nullptr, nullptr,
            gP, G4, (size_t)BATCH * G4, 256, 256);
        lstm_update<<<256, 256>>>(t);
    }

    // K = exp(HS @ W_fc^T + b_fc)   (M=32768, N=256, K=512)
    gemm_nt<2><<<dim3(4, 512, 1), 256>>>(
        gHS, LD, 0, W_fc, LD, 0, b_fc, nullptr, gK, NN, 0, LD, 0);

    // Sinkhorn: 5 x (u = 1/(Kv); v = 1/(K^T u)), then combine
    for (int it = 0; it < 5; ++it) {
        sink_row<<<dim3(32, 128), 256>>>();
        sink_col<<<dim3(4, 128), 256>>>();
    }
    sink_out<<<dim3(256, 128), 256>>>(out);
}

// round 6
// speedup vs baseline: 1.5060x; 1.5060x over previous
#include <cuda_runtime.h>
#include <math.h>

#define BATCH 128
#define NN 256
#define EMB 256
#define LD 512
#define TST 256
#define G4 2048

// ---------------- scratch (device globals; no allocations) ------------------
__device__ float g_G[(size_t)BATCH*2*NN*EMB];     // embedded g1|g2
__device__ float g_S[(size_t)BATCH*NN*NN];        // similarity
__device__ float g_XP[(size_t)BATCH*TST*G4];      // xt@W_ih^T + b_ih + b_hh (reordered)
__device__ float g_HS[(size_t)BATCH*TST*LD];      // all h_t
__device__ float g_Hb[2*BATCH*LD];                // H double buffer
__device__ float g_K[(size_t)BATCH*NN*NN];        // exp(M)
__device__ float g_u[BATCH*NN];
__device__ float g_v[BATCH*NN];
__device__ float g_Wr[G4*LD];                     // W_hh reordered (rows 4j+gate)
__device__ float g_Wi[G4*NN];                     // W_ih reordered
__device__ float g_br[G4];                        // b_ih+b_hh reordered
__device__ unsigned g_barctr;

// ---------------- packed f32x2 helpers --------------------------------------
__device__ __forceinline__ unsigned long long pk2(float lo, float hi) {
    unsigned long long r;
    asm("mov.b64 %0, {%1, %2};" : "=l"(r) : "f"(lo), "f"(hi));
    return r;
}
__device__ __forceinline__ void upk2(unsigned long long v, float &lo, float &hi) {
    asm("mov.b64 {%0, %1}, %2;" : "=f"(lo), "=f"(hi) : "l"(v));
}
__device__ __forceinline__ void fma2(unsigned long long &d, unsigned long long a,
                                     unsigned long long b) {
    asm("fma.rn.f32x2 %0, %1, %2, %0;" : "+l"(d) : "l"(a), "l"(b));
}

// ---------------- init: zero H buffers, barrier ctr; v = 1 ------------------
__global__ void init_k() {
    int i = blockIdx.x * 256 + threadIdx.x;
    if (i < 2 * BATCH * LD) g_Hb[i] = 0.f;
    if (i < BATCH * NN) g_v[i] = 1.f;
    if (i == 0) g_barctr = 0u;
}

// ---------------- reorder W_hh/W_ih rows to 4j+gate; combine biases ---------
__global__ void reorder_k(const float* __restrict__ W_ih,
                          const float* __restrict__ W_hh,
                          const float* __restrict__ b_ih,
                          const float* __restrict__ b_hh) {
    int idx = blockIdx.x * 256 + threadIdx.x;    // G4*LD = 1048576
    int R = idx >> 9, k = idx & 511;
    int j = R >> 2, gt = R & 3;
    int src = gt * 512 + j;
    g_Wr[(size_t)R * LD + k] = W_hh[(size_t)src * LD + k];
    if (k < NN) g_Wi[(size_t)R * NN + k] = W_ih[(size_t)src * NN + k];
    if (k == 0) g_br[R] = b_ih[src] + b_hh[src];
}

// ---------------- embedding + leaky relu ------------------------------------
__global__ void __launch_bounds__(256) embed_kernel(
    const float* __restrict__ x, const float* __restrict__ W_emb,
    const float* __restrict__ b_emb)
{
    __shared__ float sW[32 * 256];
    __shared__ float sx[16 * 32];
    int tid = threadIdx.x;
    int b = blockIdx.y;
    int p0 = blockIdx.x * 16;
    for (int idx = tid; idx < 256 * 32; idx += 256) {
        int e = idx >> 5, f = idx & 31;
        sW[f * 256 + e] = W_emb[idx];
    }
    for (int idx = tid; idx < 512; idx += 256)
        sx[idx] = x[((size_t)b * 512 + p0) * 32 + idx];
    __syncthreads();
    int e = tid;
    float bias = b_emb[e];
    float acc[16];
#pragma unroll
    for (int r = 0; r < 16; ++r) acc[r] = bias;
#pragma unroll
    for (int f = 0; f < 32; ++f) {
        float w = sW[f * 256 + e];
#pragma unroll
        for (int r = 0; r < 16; ++r) acc[r] += sx[r * 32 + f] * w;
    }
#pragma unroll
    for (int r = 0; r < 16; ++r) {
        float v = acc[r];
        v = (v > 0.f) ? v : 0.01f * v;
        g_G[((size_t)b * 512 + p0 + r) * 256 + e] = v;
    }
}

// ---------------- gemm128: C[m,n]=sum_k A[m,k]B[n,k]; 128x128 tile ----------
// 256 threads, 8x8 microtile (4+4 split rows/cols), f32x2 accumulators.
// MODE 0: plain   MODE 1: +bias[n]   MODE 2: exp(acc + bias[n])
template <int MODE>
__global__ void __launch_bounds__(256) gemm128(
    const float* __restrict__ A, int ldA, size_t Abat,
    const float* __restrict__ B, int ldB, size_t Bbat,
    const float* __restrict__ bias,
    float* __restrict__ C, int ldC, size_t Cbat, int K)
{
    __shared__ __align__(16) float As[16 * 128];
    __shared__ __align__(16) float Bs[16 * 128];
    int tid = threadIdx.x;
    int tx = tid & 15, ty = tid >> 4;
    size_t zo = blockIdx.z;
    A += zo * Abat + (size_t)blockIdx.y * 128 * ldA;
    B += zo * Bbat + (size_t)blockIdx.x * 128 * ldB;
    C += zo * Cbat + (size_t)blockIdx.y * 128 * ldC + (size_t)blockIdx.x * 128;

    int lrow = tid >> 1, lkq = (tid & 1) * 8;
    unsigned long long acc[8][4];
#pragma unroll
    for (int i = 0; i < 8; ++i)
#pragma unroll
        for (int j = 0; j < 4; ++j) acc[i][j] = 0ULL;

    for (int kt = 0; kt < K; kt += 16) {
        float4 av0 = *(const float4*)(A + (size_t)lrow * ldA + kt + lkq);
        float4 av1 = *(const float4*)(A + (size_t)lrow * ldA + kt + lkq + 4);
        float4 bv0 = *(const float4*)(B + (size_t)lrow * ldB + kt + lkq);
        float4 bv1 = *(const float4*)(B + (size_t)lrow * ldB + kt + lkq + 4);
        __syncthreads();
        As[(lkq + 0) * 128 + lrow] = av0.x; As[(lkq + 1) * 128 + lrow] = av0.y;
        As[(lkq + 2) * 128 + lrow] = av0.z; As[(lkq + 3) * 128 + lrow] = av0.w;
        As[(lkq + 4) * 128 + lrow] = av1.x; As[(lkq + 5) * 128 + lrow] = av1.y;
        As[(lkq + 6) * 128 + lrow] = av1.z; As[(lkq + 7) * 128 + lrow] = av1.w;
        Bs[(lkq + 0) * 128 + lrow] = bv0.x; Bs[(lkq + 1) * 128 + lrow] = bv0.y;
        Bs[(lkq + 2) * 128 + lrow] = bv0.z; Bs[(lkq + 3) * 128 + lrow] = bv0.w;
        Bs[(lkq + 4) * 128 + lrow] = bv1.x; Bs[(lkq + 5) * 128 + lrow] = bv1.y;
        Bs[(lkq + 6) * 128 + lrow] = bv1.z; Bs[(lkq + 7) * 128 + lrow] = bv1.w;
        __syncthreads();
#pragma unroll
        for (int kk = 0; kk < 16; ++kk) {
            float4 a0 = *(const float4*)&As[kk * 128 + ty * 4];
            float4 a1 = *(const float4*)&As[kk * 128 + 64 + ty * 4];
            ulonglong2 b0 = *(const ulonglong2*)&Bs[kk * 128 + tx * 4];
            ulonglong2 b1 = *(const ulonglong2*)&Bs[kk * 128 + 64 + tx * 4];
            unsigned long long ap;
            ap = pk2(a0.x, a0.x);
            fma2(acc[0][0], ap, b0.x); fma2(acc[0][1], ap, b0.y);
            fma2(acc[0][2], ap, b1.x); fma2(acc[0][3], ap, b1.y);
            ap = pk2(a0.y, a0.y);
            fma2(acc[1][0], ap, b0.x); fma2(acc[1][1], ap, b0.y);
            fma2(acc[1][2], ap, b1.x); fma2(acc[1][3], ap, b1.y);
            ap = pk2(a0.z, a0.z);
            fma2(acc[2][0], ap, b0.x); fma2(acc[2][1], ap, b0.y);
            fma2(acc[2][2], ap, b1.x); fma2(acc[2][3], ap, b1.y);
            ap = pk2(a0.w, a0.w);
            fma2(acc[3][0], ap, b0.x); fma2(acc[3][1], ap, b0.y);
            fma2(acc[3][2], ap, b1.x); fma2(acc[3][3], ap, b1.y);
            ap = pk2(a1.x, a1.x);
            fma2(acc[4][0], ap, b0.x); fma2(acc[4][1], ap, b0.y);
            fma2(acc[4][2], ap, b1.x); fma2(acc[4][3], ap, b1.y);
            ap = pk2(a1.y, a1.y);
            fma2(acc[5][0], ap, b0.x); fma2(acc[5][1], ap, b0.y);
            fma2(acc[5][2], ap, b1.x); fma2(acc[5][3], ap, b1.y);
            ap = pk2(a1.z, a1.z);
            fma2(acc[6][0], ap, b0.x); fma2(acc[6][1], ap, b0.y);
            fma2(acc[6][2], ap, b1.x); fma2(acc[6][3], ap, b1.y);
            ap = pk2(a1.w, a1.w);
            fma2(acc[7][0], ap, b0.x); fma2(acc[7][1], ap, b0.y);
            fma2(acc[7][2], ap, b1.x); fma2(acc[7][3], ap, b1.y);
        }
    }
    int nb0 = blockIdx.x * 128 + tx * 4;
#pragma unroll
    for (int i = 0; i < 8; ++i) {
        int m = (i < 4) ? (ty * 4 + i) : (64 + ty * 4 + (i - 4));
#pragma unroll
        for (int half = 0; half < 2; ++half) {
            float r0, r1, r2, r3;
            upk2(acc[i][half * 2 + 0], r0, r1);
            upk2(acc[i][half * 2 + 1], r2, r3);
            int nb = nb0 + half * 64;
            if (MODE == 1) {
                r0 += bias[nb + 0]; r1 += bias[nb + 1];
                r2 += bias[nb + 2]; r3 += bias[nb + 3];
            }
            if (MODE == 2) {
                r0 = expf(r0 + bias[nb + 0]); r1 = expf(r1 + bias[nb + 1]);
                r2 = expf(r2 + bias[nb + 2]); r3 = expf(r3 + bias[nb + 3]);
            }
            float4 o; o.x = r0; o.y = r1; o.z = r2; o.w = r3;
            *(float4*)(C + (size_t)m * ldC + tx * 4 + half * 64) = o;
        }
    }
}

// ---------------- persistent fused LSTM -------------------------------------
// 128 blocks x 256 threads, all resident. Block (rg = bid&31, bg = bid>>5):
//   owns reordered gate-rows [rg*64, rg*64+64) (= hidden j in [rg*16, rg*16+16))
//   and batches [bg*32, bg*32+32). W slice in smem for all 256 steps; c in regs.
// Per step: load H tile (32x512) -> smem; 8 warps split K (64 each); 8x8
// microtile f32x2; smem partial reduce; fused gate update; global barrier.
#define WS_STRIDE 516
#define PART_WSTRIDE 2304        /* per-warp partial region: r*36+b, max 2299 */
#define LSTM_SMEM ((64 * WS_STRIDE + 8 * PART_WSTRIDE) * 4)

__global__ void __launch_bounds__(256, 1) lstm_persist(
    const float* __restrict__ XP, const float* __restrict__ Wr,
    float* __restrict__ HS)
{
    extern __shared__ float sm[];
    float* Ws = sm;                        // 64 x 516
    float* Hs = sm + 64 * WS_STRIDE;       // 32 x 516 (first part of part region)
    float* part = Hs;                      // 8 x 2304 (reused after k-loop)

    int tid = threadIdx.x;
    int rg = blockIdx.x & 31;
    int bg = blockIdx.x >> 5;
    int warp = tid >> 5;
    int lane = tid & 31;
    int bq = lane & 3;
    int rq = (lane >> 2) & 7;
    int kbase = warp * 64;

    // load W slice once (64 rows x 512)
    for (int i = tid; i < 64 * 128; i += 256) {
        int r = i >> 7, kq = (i & 127) * 4;
        float4 v = *(const float4*)&Wr[(size_t)(rg * 64 + r) * LD + kq];
        *(float4*)&Ws[r * WS_STRIDE + kq] = v;
    }

    // per-thread update pairs + register cell state
    int p0 = tid * 2, p1 = tid * 2 + 1;
    int bl0 = p0 & 31, h0 = p0 >> 5;
    int bl1 = p1 & 31, h1 = p1 >> 5;
    float c0 = 0.f, c1 = 0.f;

    __syncthreads();

    for (int s = 0; s < TST; ++s) {
        const float* Hr = g_Hb + (size_t)(s & 1) * (BATCH * LD);
        float* Hw = g_Hb + (size_t)((s + 1) & 1) * (BATCH * LD);

        // stage H tile: batches [bg*32, +32), all 512
        for (int i = tid; i < 32 * 128; i += 256) {
            int b = i >> 7, kq = (i & 127) * 4;
            float4 v = *(const float4*)&Hr[(size_t)(bg * 32 + b) * LD + kq];
            *(float4*)&Hs[b * WS_STRIDE + kq] = v;
        }
        __syncthreads();

        unsigned long long acc[8][8];
#pragma unroll
        for (int i = 0; i < 8; ++i)
#pragma unroll
            for (int j = 0; j < 8; ++j) acc[i][j] = 0ULL;

#pragma unroll 1
        for (int q = 0; q < 16; ++q) {
            int k = kbase + q * 4;
            ulonglong2 h4[8], w4[8];
#pragma unroll
            for (int i = 0; i < 8; ++i)
                h4[i] = *(const ulonglong2*)&Hs[(bq + 4 * i) * WS_STRIDE + k];
#pragma unroll
            for (int j = 0; j < 8; ++j)
                w4[j] = *(const ulonglong2*)&Ws[(rq + 8 * j) * WS_STRIDE + k];
#pragma unroll
            for (int i = 0; i < 8; ++i)
#pragma unroll
                for (int j = 0; j < 8; ++j) {
                    fma2(acc[i][j], h4[i].x, w4[j].x);
                    fma2(acc[i][j], h4[i].y, w4[j].y);
                }
        }
        __syncthreads();   // all warps done reading Hs before overwrite

        // write partials: part[warp][r*36 + b]
#pragma unroll
        for (int i = 0; i < 8; ++i)
#pragma unroll
            for (int j = 0; j < 8; ++j) {
                float lo, hi; upk2(acc[i][j], lo, hi);
                part[warp * PART_WSTRIDE + (rq + 8 * j) * 36 + (bq + 4 * i)] = lo + hi;
            }
        __syncthreads();

        // reduce across 8 warps + LSTM update (2 (batch,hidden) pairs/thread)
        {
            float4 g0 = *(const float4*)&XP[
                ((size_t)(bg * 32 + bl0) * TST + s) * G4 + rg * 64 + 4 * h0];
            float4 g1v = *(const float4*)&XP[
                ((size_t)(bg * 32 + bl1) * TST + s) * G4 + rg * 64 + 4 * h1];
#pragma unroll
            for (int w = 0; w < 8; ++w) {
                const float* pw = part + w * PART_WSTRIDE;
                int r0 = 4 * h0, r1 = 4 * h1;
                g0.x += pw[(r0 + 0) * 36 + bl0];
                g0.y += pw[(r0 + 1) * 36 + bl0];
                g0.z += pw[(r0 + 2) * 36 + bl0];
                g0.w += pw[(r0 + 3) * 36 + bl0];
                g1v.x += pw[(r1 + 0) * 36 + bl1];
                g1v.y += pw[(r1 + 1) * 36 + bl1];
                g1v.z += pw[(r1 + 2) * 36 + bl1];
                g1v.w += pw[(r1 + 3) * 36 + bl1];
            }
            // gates order per hidden: [i, f, g, o]
            float i_, f_, gg, o_, h;
            i_ = 1.f / (1.f + __expf(-g0.x));
            f_ = 1.f / (1.f + __expf(-g0.y));
            gg = tanhf(g0.z);
            o_ = 1.f / (1.f + __expf(-g0.w));
            c0 = f_ * c0 + i_ * gg;
            h = o_ * tanhf(c0);
            {
                int bgl = bg * 32 + bl0, jg = rg * 16 + h0;
                Hw[(size_t)bgl * LD + jg] = h;
                HS[((size_t)bgl * TST + s) * LD + jg] = h;
            }
            i_ = 1.f / (1.f + __expf(-g1v.x));
            f_ = 1.f / (1.f + __expf(-g1v.y));
            gg = tanhf(g1v.z);
            o_ = 1.f / (1.f + __expf(-g1v.w));
            c1 = f_ * c1 + i_ * gg;
            h = o_ * tanhf(c1);
            {
                int bgl = bg * 32 + bl1, jg = rg * 16 + h1;
                Hw[(size_t)bgl * LD + jg] = h;
                HS[((size_t)bgl * TST + s) * LD + jg] = h;
            }
        }

        // grid-wide barrier (counter, monotonic targets; no reset mid-kernel)
        __syncthreads();
        if (tid == 0) {
            __threadfence();
            atomicAdd(&g_barctr, 1u);
            unsigned tgt = 128u * (unsigned)(s + 1);
            unsigned v;
            do {
                asm volatile("ld.acquire.gpu.global.u32 %0, [%1];"
                             : "=r"(v) : "l"(&g_barctr));
            } while (v < tgt);
        }
        __syncthreads();
    }
}

// ---------------- Sinkhorn (u = 1/(Kv), v = 1/(K^T u)) ----------------------
__global__ void sink_row() {
    int b = blockIdx.y;
    int m = blockIdx.x * 8 + (threadIdx.x >> 5);
    int lane = threadIdx.x & 31;
    const float* Kr = g_K + ((size_t)b * NN + m) * NN;
    const float* vv = g_v + b * NN;
    float acc = 0.f;
#pragma unroll
    for (int i = 0; i < 8; ++i) acc += Kr[lane + 32 * i] * vv[lane + 32 * i];
#pragma unroll
    for (int o = 16; o; o >>= 1) acc += __shfl_xor_sync(0xFFFFFFFFu, acc, o);
    if (!lane) g_u[b * NN + m] = 1.f / acc;
}

__global__ void sink_col() {
    int b = blockIdx.y;
    int n = blockIdx.x * 64 + (threadIdx.x & 63);
    int part = threadIdx.x >> 6;
    const float* Kb = g_K + (size_t)b * NN * NN;
    const float* uu = g_u + b * NN;
    float acc = 0.f;
    for (int m = part; m < NN; m += 4) acc += Kb[(size_t)m * NN + n] * uu[m];
    __shared__ float s[256];
    s[threadIdx.x] = acc;
    __syncthreads();
    if (threadIdx.x < 64) {
        float r = s[threadIdx.x] + s[threadIdx.x + 64] + s[threadIdx.x + 128] +
                  s[threadIdx.x + 192];
        g_v[b * NN + n] = 1.f / r;
    }
}

__global__ void sink_out(float* __restrict__ out) {
    int b = blockIdx.y, m = blockIdx.x, n = threadIdx.x;
    size_t o = ((size_t)b * NN + m) * NN + n;
    out[o] = g_u[b * NN + m] * g_K[o] * g_v[b * NN + n];
}

// ---------------------------------------------------------------------------
extern "C" void kernel_launch(void* const* d_in, const int* in_sizes, int n_in,
                              void* d_out, int out_size)
{
    const float* x     = (const float*)d_in[0];
    const float* W_emb = (const float*)d_in[1];
    const float* b_emb = (const float*)d_in[2];
    const float* W_ih  = (const float*)d_in[3];
    const float* W_hh  = (const float*)d_in[4];
    const float* b_ih  = (const float*)d_in[5];
    const float* b_hh  = (const float*)d_in[6];
    const float* W_fc  = (const float*)d_in[7];
    const float* b_fc  = (const float*)d_in[8];
    float* out = (float*)d_out;

    float *gG, *gS, *gXP, *gHS, *gK, *gWr, *gWi, *gbr;
    cudaGetSymbolAddress((void**)&gG,  g_G);
    cudaGetSymbolAddress((void**)&gS,  g_S);
    cudaGetSymbolAddress((void**)&gXP, g_XP);
    cudaGetSymbolAddress((void**)&gHS, g_HS);
    cudaGetSymbolAddress((void**)&gK,  g_K);
    cudaGetSymbolAddress((void**)&gWr, g_Wr);
    cudaGetSymbolAddress((void**)&gWi, g_Wi);
    cudaGetSymbolAddress((void**)&gbr, g_br);

    static bool attr_set = false;
    if (!attr_set) {
        cudaFuncSetAttribute(lstm_persist,
                             cudaFuncAttributeMaxDynamicSharedMemorySize,
                             LSTM_SMEM);
        attr_set = true;
    }

    init_k<<<512, 256>>>();
    reorder_k<<<4096, 256>>>(W_ih, W_hh, b_ih, b_hh);
    embed_kernel<<<dim3(32, 128), 256>>>(x, W_emb, b_emb);

    // S[b] = g2[b] @ g1[b]^T   (M=N=256, K=256, batched over 128)
    gemm128<0><<<dim3(2, 2, 128), 256>>>(
        gG + (size_t)NN * EMB, EMB, (size_t)2 * NN * EMB,
        gG, EMB, (size_t)2 * NN * EMB,
        nullptr, gS, NN, (size_t)NN * NN, EMB);

    // XP[(b,t), R] = S_row @ g_Wi^T + g_br   (M=32768, N=2048, K=256)
    gemm128<1><<<dim3(16, 256, 1), 256>>>(
        gS, NN, 0, gWi, NN, 0, gbr, gXP, G4, 0, NN);

    // fused persistent LSTM: 256 steps in one launch
    lstm_persist<<<128, 256, LSTM_SMEM>>>(gXP, gWr, gHS);

    // K = exp(HS @ W_fc^T + b_fc)   (M=32768, N=256, K=512)
    gemm128<2><<<dim3(2, 256, 1), 256>>>(
        gHS, LD, 0, W_fc, LD, 0, b_fc, gK, NN, 0, LD);

    // Sinkhorn: 5 x (u = 1/(Kv); v = 1/(K^T u)), then combine
    for (int it = 0; it < 5; ++it) {
        sink_row<<<dim3(32, 128), 256>>>();
        sink_col<<<dim3(4, 128), 256>>>();
    }
    sink_out<<<dim3(256, 128), 256>>>(out);
}